// round 5
// baseline (speedup 1.0000x reference)
#include <cuda_runtime.h>
#include <cstdint>

// Problem constants
#define BB 8
#define NN 2048
#define IND 128
#define OUTD 64
#define NEG_SLOPE 0.2f

// Scratch (device globals: no allocation allowed)
__device__ float g_hp[BB * NN * OUTD];   // projected features (4 MB)
__device__ float g_s[BB * NN];           // hp @ a_src  (+ b_attn folded in)
__device__ float g_d[BB * NN];           // hp @ a_dst
__device__ float g_dmax[BB];             // per-batch max of d

// ---------- packed f32x2 helpers ----------
__device__ __forceinline__ unsigned long long fma2(unsigned long long a,
                                                   unsigned long long b,
                                                   unsigned long long c) {
    unsigned long long d;
    asm("fma.rn.f32x2 %0, %1, %2, %3;" : "=l"(d) : "l"(a), "l"(b), "l"(c));
    return d;
}
__device__ __forceinline__ unsigned long long pk2(float a, float b) {
    unsigned long long u;
    asm("mov.b64 %0, {%1, %2};" : "=l"(u) : "f"(a), "f"(b));
    return u;
}
__device__ __forceinline__ void upk2(unsigned long long u, float& lo, float& hi) {
    asm("mov.b64 {%0, %1}, %2;" : "=f"(lo), "=f"(hi) : "l"(u));
}

// ============================================================
// Kernel 1: hp = h @ W + b ; s = hp@a_src + b_attn ; d = hp@a_dst
// grid 128 blocks x 128 threads, 1 row per thread
// ============================================================
__global__ __launch_bounds__(128) void k_proj(
    const float* __restrict__ h, const float* __restrict__ W,
    const float* __restrict__ bfc, const float* __restrict__ asrc,
    const float* __restrict__ adst, const float* __restrict__ battn) {
    __shared__ __align__(16) float sW[IND * OUTD];
    __shared__ float sb[OUTD], sas[OUTD], sad[OUTD];
    int tid = threadIdx.x;

    for (int v = tid; v < IND * OUTD / 4; v += 128)
        ((float4*)sW)[v] = ((const float4*)W)[v];
    if (tid < OUTD) { sb[tid] = bfc[tid]; sas[tid] = asrc[tid]; sad[tid] = adst[tid]; }
    __syncthreads();

    int row = blockIdx.x * 128 + tid;   // 0..16383
    float acc[OUTD];
#pragma unroll
    for (int c = 0; c < OUTD; c++) acc[c] = sb[c];

    const float4* h4 = (const float4*)(h + (size_t)row * IND);
    for (int k4 = 0; k4 < IND / 4; k4++) {
        float4 hv = h4[k4];
        float hk[4] = {hv.x, hv.y, hv.z, hv.w};
#pragma unroll
        for (int kk = 0; kk < 4; kk++) {
            const float4* wrow = (const float4*)(sW + (k4 * 4 + kk) * OUTD);
#pragma unroll
            for (int c4 = 0; c4 < OUTD / 4; c4++) {
                float4 wv = wrow[c4];
                acc[c4 * 4 + 0] = fmaf(hk[kk], wv.x, acc[c4 * 4 + 0]);
                acc[c4 * 4 + 1] = fmaf(hk[kk], wv.y, acc[c4 * 4 + 1]);
                acc[c4 * 4 + 2] = fmaf(hk[kk], wv.z, acc[c4 * 4 + 2]);
                acc[c4 * 4 + 3] = fmaf(hk[kk], wv.w, acc[c4 * 4 + 3]);
            }
        }
    }

    float s = battn[0], d = 0.f;
#pragma unroll
    for (int c = 0; c < OUTD; c++) {
        s = fmaf(acc[c], sas[c], s);
        d = fmaf(acc[c], sad[c], d);
    }
    g_s[row] = s;
    g_d[row] = d;
    float4* o4 = (float4*)(g_hp + (size_t)row * OUTD);
#pragma unroll
    for (int c4 = 0; c4 < OUTD / 4; c4++)
        o4[c4] = make_float4(acc[c4 * 4], acc[c4 * 4 + 1], acc[c4 * 4 + 2], acc[c4 * 4 + 3]);
}

// ============================================================
// Kernel 2: per-batch max of d (8 blocks x 256 threads)
// ============================================================
__global__ void k_dmax() {
    __shared__ float sm[256];
    int b = blockIdx.x, tid = threadIdx.x;
    float m = -1e30f;
    for (int j = tid; j < NN; j += 256) m = fmaxf(m, g_d[b * NN + j]);
    sm[tid] = m;
    __syncthreads();
    for (int off = 128; off > 0; off >>= 1) {
        if (tid < off) sm[tid] = fmaxf(sm[tid], sm[tid + off]);
        __syncthreads();
    }
    if (tid == 0) g_dmax[b] = sm[0];
}

// ============================================================
// Kernel 3: fused scores -> leaky -> softmax -> attn@hp -> elu
// grid (N/64, B), 128 threads. I_TILE=64, J_TILE=64.
// Thread MMA tile: 4 i-rows x 8 cols (as 4 f32x2 pairs).
// ============================================================
__global__ __launch_bounds__(128) void k_attn(float* __restrict__ out) {
    __shared__ __align__(16) float s_hp[64 * 64];   // hp tile [j][c]
    __shared__ __align__(16) float s_w[64 * 64];    // weights [j][i]
    __shared__ float s_sum[128];                    // partial row sums of w

    const int b = blockIdx.y;
    const int i0 = blockIdx.x * 64;
    const int tid = threadIdx.x;

    // w-phase identity: fixed local row iw, parity half
    const int iw = tid & 63;
    const int half = tid >> 6;
    // mma-phase identity: 4-row group ig, 8-col group cg
    const int ig = tid & 15;
    const int cg = tid >> 4;

    const float si = g_s[b * NN + i0 + iw];          // includes b_attn
    const float dmax = g_dmax[b];
    const float tmax = si + dmax;
    const float mi = tmax >= 0.f ? tmax : NEG_SLOPE * tmax;  // exact row max of scores

    const float* __restrict__ hpB = g_hp + (size_t)b * NN * OUTD;
    const float* __restrict__ dB = g_d + b * NN;

    unsigned long long acc[16];
#pragma unroll
    for (int i = 0; i < 16; i++) acc[i] = 0ull;  // bits of (0.f, 0.f)
    float wsum = 0.f;

    for (int jt = 0; jt < NN / 64; jt++) {
        const int j0 = jt * 64;
        __syncthreads();  // previous tile fully consumed

        // stage hp tile (64x64 f32) coalesced
#pragma unroll
        for (int v = 0; v < 8; v++) {
            int lin = v * 128 + tid;       // float4 index 0..1023
            int row = lin >> 4, c4 = lin & 15;
            ((float4*)s_hp)[row * 16 + c4] =
                ((const float4*)(hpB + (size_t)(j0 + row) * OUTD))[c4];
        }
        // compute exp weights for this thread's (iw, parity) slice
#pragma unroll
        for (int r = 0; r < 32; r++) {
            int j = half + 2 * r;
            float t = si + dB[j0 + j];
            float sc = t >= 0.f ? t : NEG_SLOPE * t;
            float w = __expf(sc - mi);
            wsum += w;
            s_w[j * 64 + iw] = w;
        }
        __syncthreads();

        // register-tiled (64x64)@(64x64) with packed f32x2 FMA
        const float* wp = s_w + ig * 4;
        const float* hq = s_hp + cg * 8;
#pragma unroll 8
        for (int j = 0; j < 64; j++) {
            float4 wv = *(const float4*)(wp + j * 64);
            ulonglong2 ha = *(const ulonglong2*)(hq + j * 64);       // (c0,c1),(c2,c3)
            ulonglong2 hb = *(const ulonglong2*)(hq + j * 64 + 4);   // (c4,c5),(c6,c7)
            float wa[4] = {wv.x, wv.y, wv.z, wv.w};
#pragma unroll
            for (int ii = 0; ii < 4; ii++) {
                unsigned long long ww = pk2(wa[ii], wa[ii]);
                acc[ii * 4 + 0] = fma2(ww, ha.x, acc[ii * 4 + 0]);
                acc[ii * 4 + 1] = fma2(ww, ha.y, acc[ii * 4 + 1]);
                acc[ii * 4 + 2] = fma2(ww, hb.x, acc[ii * 4 + 2]);
                acc[ii * 4 + 3] = fma2(ww, hb.y, acc[ii * 4 + 3]);
            }
        }
    }

    __syncthreads();
    s_sum[half * 64 + iw] = wsum;   // each thread owns (row, parity)
    __syncthreads();

    // epilogue: normalize, elu, store
#pragma unroll
    for (int ii = 0; ii < 4; ii++) {
        int il = ig * 4 + ii;
        float tot = s_sum[il] + s_sum[64 + il];
        float inv = 1.0f / tot;
        float o[8];
#pragma unroll
        for (int p = 0; p < 4; p++) upk2(acc[ii * 4 + p], o[2 * p], o[2 * p + 1]);
#pragma unroll
        for (int c = 0; c < 8; c++) {
            float v = o[c] * inv;
            o[c] = v > 0.f ? v : (__expf(v) - 1.0f);  // elu
        }
        float* dst = out + ((size_t)(b * NN + i0 + il)) * OUTD + cg * 8;
        *(float4*)dst = make_float4(o[0], o[1], o[2], o[3]);
        *(float4*)(dst + 4) = make_float4(o[4], o[5], o[6], o[7]);
    }
}

extern "C" void kernel_launch(void* const* d_in, const int* in_sizes, int n_in,
                              void* d_out, int out_size) {
    const float* h = (const float*)d_in[0];
    const float* W = (const float*)d_in[1];
    const float* bfc = (const float*)d_in[2];
    const float* asrc = (const float*)d_in[3];
    const float* adst = (const float*)d_in[4];
    const float* battn = (const float*)d_in[5];
    float* out = (float*)d_out;

    k_proj<<<BB * NN / 128, 128>>>(h, W, bfc, asrc, adst, battn);
    k_dmax<<<BB, 256>>>();
    k_attn<<<dim3(NN / 64, BB), 128>>>(out);
}